// round 1
// baseline (speedup 1.0000x reference)
#include <cuda_runtime.h>
#include <math.h>

#define NB 64
#define NT 512
#define NC 768
#define NH 192
#define ROT 32
#define M_TOT (NB*NT)

// Scratch for projected q, k, v (device globals: no allocation at launch time)
__device__ float g_q[M_TOT * NH];
__device__ float g_k[M_TOT * NH];
__device__ float g_v[M_TOT * NH];

// ============================================================================
// QKV projection GEMM: out = X(32768,768) @ W(768,192), RoPE fused for q,k
// 64x64 tile, BK=16, 256 threads, 4x4 register blocking
// ============================================================================
#define BM 64
#define BN 64
#define BK 16
#define LDA 68   // padded to break store bank conflicts, keeps float4 alignment

__global__ __launch_bounds__(256)
void qkv_gemm(const float* __restrict__ X, const float* __restrict__ W, int which)
{
    __shared__ float As[BK * LDA];   // [k][m]
    __shared__ float Bs[BK * BN];    // [k][n]

    float* outp = (which == 0) ? g_q : (which == 1) ? g_k : g_v;
    const bool rope = (which < 2);

    const int tx = threadIdx.x & 15;
    const int ty = threadIdx.x >> 4;
    const int m0 = blockIdx.y * BM;
    const int n0 = blockIdx.x * BN;

    // loader indices
    const int lr = threadIdx.x >> 2;   // 0..63 : A row within tile
    const int lc = threadIdx.x & 3;    // 0..3  : A float4 col group
    const int wr = threadIdx.x >> 4;   // 0..15 : B row within tile
    const int wc = threadIdx.x & 15;   // 0..15 : B float4 col group

    const float* Xp = X + (size_t)(m0 + lr) * NC + lc * 4;
    const float* Wp = W + (size_t)wr * NH + n0 + wc * 4;

    float acc[4][4];
    #pragma unroll
    for (int i = 0; i < 4; i++)
        #pragma unroll
        for (int j = 0; j < 4; j++) acc[i][j] = 0.f;

    for (int k0 = 0; k0 < NC; k0 += BK) {
        float4 a = *(const float4*)(Xp + k0);
        float4 b = *(const float4*)(Wp + (size_t)k0 * NH);
        As[(lc * 4 + 0) * LDA + lr] = a.x;
        As[(lc * 4 + 1) * LDA + lr] = a.y;
        As[(lc * 4 + 2) * LDA + lr] = a.z;
        As[(lc * 4 + 3) * LDA + lr] = a.w;
        *(float4*)&Bs[wr * BN + wc * 4] = b;
        __syncthreads();

        #pragma unroll
        for (int kk = 0; kk < BK; kk++) {
            float4 av = *(const float4*)&As[kk * LDA + ty * 4];
            float4 bv = *(const float4*)&Bs[kk * BN + tx * 4];
            float aa[4] = {av.x, av.y, av.z, av.w};
            float bb[4] = {bv.x, bv.y, bv.z, bv.w};
            #pragma unroll
            for (int i = 0; i < 4; i++)
                #pragma unroll
                for (int j = 0; j < 4; j++)
                    acc[i][j] += aa[i] * bb[j];
        }
        __syncthreads();
    }

    // epilogue: optional RoPE on cols < 32, then store
    const int colb = n0 + tx * 4;
    const float LOG2_THETA = 13.287712379549449f;  // log2(10000)

    #pragma unroll
    for (int i = 0; i < 4; i++) {
        int row = m0 + ty * 4 + i;
        if (rope && colb < ROT) {
            int t = row & (NT - 1);
            #pragma unroll
            for (int jp = 0; jp < 4; jp += 2) {
                int d  = colb + jp;
                int jh = d >> 1;
                float inv = exp2f(-(float)(2 * jh) * (1.0f / 32.0f) * LOG2_THETA);
                float ang = (float)t * inv;
                float sn, cs;
                sincosf(ang, &sn, &cs);
                float x1 = acc[i][jp], x2 = acc[i][jp + 1];
                acc[i][jp]     = x1 * cs - x2 * sn;
                acc[i][jp + 1] = x2 * cs + x1 * sn;
            }
        }
        float4 o = make_float4(acc[i][0], acc[i][1], acc[i][2], acc[i][3]);
        *(float4*)&outp[(size_t)row * NH + colb] = o;
    }
}

// ============================================================================
// Flash-style causal attention, fp32.
// Block = (batch b, query tile qt of 64 rows). 256 threads.
// ============================================================================
#define BQ  64
#define BKT 64
#define LDK 68   // K^T smem leading dim (pad, float4-aligned)
#define LDS2 68  // scores smem leading dim

#define ATTN_SMEM_FLOATS (BQ*NH + NH*LDK + BKT*NH + BQ*LDS2 + 3*BQ)

__global__ __launch_bounds__(256)
void attn_kernel(float* __restrict__ out)
{
    extern __shared__ float sm[];
    float* Qs  = sm;                 // [64][192]
    float* Kst = Qs  + BQ * NH;      // [192][LDK]  (K transposed)
    float* Vs  = Kst + NH * LDK;     // [64][192]
    float* Ss  = Vs  + BKT * NH;     // [64][LDS2]
    float* m_s = Ss  + BQ * LDS2;    // [64]
    float* l_s = m_s + BQ;           // [64]
    float* c_s = l_s + BQ;           // [64]

    const int b   = blockIdx.y;
    const int qt  = gridDim.x - 1 - blockIdx.x;   // heavy tiles first
    const int q0  = qt * BQ;
    const int tid = threadIdx.x;
    const int tx  = tid & 15;
    const int ty  = tid >> 4;

    // load Q tile (contiguous 64*192 floats)
    {
        const float4* src = (const float4*)(g_q + ((size_t)b * NT + q0) * NH);
        float4* dst = (float4*)Qs;
        #pragma unroll
        for (int i = 0; i < 12; i++)
            dst[tid + i * 256] = src[tid + i * 256];
    }
    if (tid < BQ) { m_s[tid] = -INFINITY; l_s[tid] = 0.f; }

    float o[4][12];
    #pragma unroll
    for (int i = 0; i < 4; i++)
        #pragma unroll
        for (int j = 0; j < 12; j++) o[i][j] = 0.f;

    const float scale = 1.0f / sqrtf((float)NH);

    for (int kt = 0; kt <= qt; kt++) {
        __syncthreads();   // previous PV phase done before overwriting K/V

        const float* kb = g_k + ((size_t)b * NT + kt * BKT) * NH;
        const float* vb = g_v + ((size_t)b * NT + kt * BKT) * NH;
        // K transposed into smem
        for (int e = tid; e < BKT * NH; e += 256) {
            int c = e / NH;
            int h = e - c * NH;
            Kst[h * LDK + c] = kb[e];
        }
        // V natural layout
        {
            const float4* src = (const float4*)vb;
            float4* dst = (float4*)Vs;
            #pragma unroll
            for (int i = 0; i < 12; i++)
                dst[tid + i * 256] = src[tid + i * 256];
        }
        __syncthreads();

        // ---- S = Q K^T (each thread: 4x4 fragment) ----
        float s[4][4];
        #pragma unroll
        for (int i = 0; i < 4; i++)
            #pragma unroll
            for (int j = 0; j < 4; j++) s[i][j] = 0.f;

        #pragma unroll 2
        for (int h = 0; h < NH; h += 4) {
            float av[4][4];
            #pragma unroll
            for (int i = 0; i < 4; i++) {
                float4 t4 = *(const float4*)&Qs[(ty * 4 + i) * NH + h];
                av[i][0] = t4.x; av[i][1] = t4.y; av[i][2] = t4.z; av[i][3] = t4.w;
            }
            #pragma unroll
            for (int u = 0; u < 4; u++) {
                float4 bv = *(const float4*)&Kst[(h + u) * LDK + tx * 4];
                float bb[4] = {bv.x, bv.y, bv.z, bv.w};
                #pragma unroll
                for (int i = 0; i < 4; i++)
                    #pragma unroll
                    for (int j = 0; j < 4; j++)
                        s[i][j] += av[i][u] * bb[j];
            }
        }

        // mask + scale, write scores to smem
        const bool diag = (kt == qt);
        #pragma unroll
        for (int i = 0; i < 4; i++) {
            int rq = ty * 4 + i;
            #pragma unroll
            for (int j = 0; j < 4; j++) {
                int c = tx * 4 + j;
                float v = s[i][j] * scale;
                if (diag && c > rq) v = -INFINITY;
                Ss[rq * LDS2 + c] = v;
            }
        }
        __syncthreads();

        // ---- online softmax: one thread per row ----
        if (tid < BQ) {
            int r = tid;
            float mo = m_s[r];
            float rmax = mo;
            #pragma unroll 8
            for (int c = 0; c < BKT; c++)
                rmax = fmaxf(rmax, Ss[r * LDS2 + c]);
            float corr = expf(mo - rmax);     // 0 on first tile (mo = -inf)
            float sum = 0.f;
            #pragma unroll 8
            for (int c = 0; c < BKT; c++) {
                float p = expf(Ss[r * LDS2 + c] - rmax);
                Ss[r * LDS2 + c] = p;
                sum += p;
            }
            l_s[r] = l_s[r] * corr + sum;
            m_s[r] = rmax;
            c_s[r] = corr;
        }
        __syncthreads();

        // ---- rescale O, accumulate P V ----
        #pragma unroll
        for (int i = 0; i < 4; i++) {
            float corr = c_s[ty * 4 + i];
            #pragma unroll
            for (int j = 0; j < 12; j++) o[i][j] *= corr;
        }
        #pragma unroll 2
        for (int kk = 0; kk < BKT; kk++) {
            float p[4];
            #pragma unroll
            for (int i = 0; i < 4; i++)
                p[i] = Ss[(ty * 4 + i) * LDS2 + kk];
            #pragma unroll
            for (int j = 0; j < 12; j++) {
                float vv = Vs[kk * NH + tx + 16 * j];
                #pragma unroll
                for (int i = 0; i < 4; i++)
                    o[i][j] += p[i] * vv;
            }
        }
    }

    // ---- finalize: O / l, store ----
    float* ob = out + ((size_t)b * NT + q0) * NH;
    #pragma unroll
    for (int i = 0; i < 4; i++) {
        int r = ty * 4 + i;
        float inv_l = 1.0f / l_s[r];
        #pragma unroll
        for (int j = 0; j < 12; j++)
            ob[(size_t)r * NH + tx + 16 * j] = o[i][j] * inv_l;
    }
}

// ============================================================================
// Launch
// ============================================================================
extern "C" void kernel_launch(void* const* d_in, const int* in_sizes, int n_in,
                              void* d_out, int out_size)
{
    const float* x  = (const float*)d_in[0];
    const float* Wq = (const float*)d_in[1];
    const float* Wk = (const float*)d_in[2];
    const float* Wv = (const float*)d_in[3];
    float* out = (float*)d_out;

    (void)in_sizes; (void)n_in; (void)out_size;

    // QKV projections (+RoPE fused for q,k)
    dim3 gblk(256);
    dim3 ggrd(NH / BN, M_TOT / BM);   // (3, 512)
    qkv_gemm<<<ggrd, gblk>>>(x, Wq, 0);
    qkv_gemm<<<ggrd, gblk>>>(x, Wk, 1);
    qkv_gemm<<<ggrd, gblk>>>(x, Wv, 2);

    // Attention
    size_t smem = ATTN_SMEM_FLOATS * sizeof(float);
    cudaFuncSetAttribute(attn_kernel, cudaFuncAttributeMaxDynamicSharedMemorySize, (int)smem);
    dim3 agrd(NT / BQ, NB);           // (8, 64)
    attn_kernel<<<agrd, 256, smem>>>(out);
}

// round 2
// speedup vs baseline: 1.7340x; 1.7340x over previous
#include <cuda_runtime.h>
#include <math.h>

#define NB 64
#define NT 512
#define NC 768
#define NH 192
#define ROT 32
#define M_TOT (NB*NT)

// Scratch for projected q, k, v (device globals: no allocation at launch time)
__device__ float g_q[M_TOT * NH];
__device__ float g_k[M_TOT * NH];
__device__ float g_v[M_TOT * NH];

// ============================================================================
// tf32 helpers
// ============================================================================
__device__ __forceinline__ float f2tf32(float x) {
    unsigned u;
    asm("cvt.rna.tf32.f32 %0, %1;" : "=r"(u) : "f"(x));
    return __uint_as_float(u);
}

// ============================================================================
// QKV projection: out = X(32768,768) @ W(768,192), RoPE fused for q,k.
// tf32 mma.sync.m16n8k8. Block tile 128x64, BK=16, 256 threads (8 warps 4x2),
// warp tile 32x32 = 2(M) x 4(N) mma tiles.
// ============================================================================
#define GBM 128
#define GBN 64
#define GBK 16
#define LDA 20   // As row stride (floats): conflict-free frag reads
#define LDB 72   // Bs row stride: t*72+g ≡ t*8+g mod 32, conflict-free

__global__ __launch_bounds__(256)
void qkv_mma(const float* __restrict__ X,
             const float* __restrict__ Wq,
             const float* __restrict__ Wk,
             const float* __restrict__ Wv)
{
    __shared__ float As[GBM * LDA];   // [m][k]
    __shared__ float Bs[GBK * LDB];   // [k][n]

    const int which = blockIdx.z;
    const float* W  = (which == 0) ? Wq : (which == 1) ? Wk : Wv;
    float* outp     = (which == 0) ? g_q : (which == 1) ? g_k : g_v;
    const bool rope = (which < 2);

    const int m0 = blockIdx.y * GBM;
    const int n0 = blockIdx.x * GBN;

    const int tid  = threadIdx.x;
    const int lane = tid & 31;
    const int wid  = tid >> 5;
    const int wm   = (wid & 3) * 32;   // warp M offset in tile
    const int wn   = (wid >> 2) * 32;  // warp N offset in tile
    const int g    = lane >> 2;        // groupID 0..7
    const int t    = lane & 3;         // thread-in-group 0..3

    // global loader indices
    const int am = tid >> 2;           // 0..63 (A rows; +64 second half)
    const int ak = (tid & 3) * 4;      // A k quad
    const int bk = tid >> 4;           // 0..15 (B k row)
    const int bn = (tid & 15) * 4;     // B n quad

    const float* Ag = X + (size_t)(m0 + am) * NC + ak;
    const float* Bg = W + (size_t)bk * NH + n0 + bn;

    float4 ra0, ra1, rb;

    float c[2][4][4];
    #pragma unroll
    for (int mi = 0; mi < 2; mi++)
        #pragma unroll
        for (int ni = 0; ni < 4; ni++)
            #pragma unroll
            for (int r = 0; r < 4; r++) c[mi][ni][r] = 0.f;

    const int K_TILES = NC / GBK;   // 48

    // prologue: load tile 0
    ra0 = *(const float4*)(Ag);
    ra1 = *(const float4*)(Ag + 64 * NC);
    rb  = *(const float4*)(Bg);
    {
        As[am * LDA + ak + 0] = f2tf32(ra0.x);
        As[am * LDA + ak + 1] = f2tf32(ra0.y);
        As[am * LDA + ak + 2] = f2tf32(ra0.z);
        As[am * LDA + ak + 3] = f2tf32(ra0.w);
        As[(am + 64) * LDA + ak + 0] = f2tf32(ra1.x);
        As[(am + 64) * LDA + ak + 1] = f2tf32(ra1.y);
        As[(am + 64) * LDA + ak + 2] = f2tf32(ra1.z);
        As[(am + 64) * LDA + ak + 3] = f2tf32(ra1.w);
        Bs[bk * LDB + bn + 0] = f2tf32(rb.x);
        Bs[bk * LDB + bn + 1] = f2tf32(rb.y);
        Bs[bk * LDB + bn + 2] = f2tf32(rb.z);
        Bs[bk * LDB + bn + 3] = f2tf32(rb.w);
    }
    __syncthreads();

    for (int kt = 0; kt < K_TILES; kt++) {
        const bool more = (kt + 1 < K_TILES);
        if (more) {
            int k0 = (kt + 1) * GBK;
            ra0 = *(const float4*)(Ag + k0);
            ra1 = *(const float4*)(Ag + 64 * NC + k0);
            rb  = *(const float4*)(Bg + (size_t)k0 * NH);
        }

        // compute: 2 k-steps of 8
        #pragma unroll
        for (int ks = 0; ks < GBK; ks += 8) {
            unsigned af[2][4];
            unsigned bf[4][2];
            #pragma unroll
            for (int mi = 0; mi < 2; mi++) {
                int r0 = (wm + mi * 16 + g) * LDA + ks + t;
                int r1 = (wm + mi * 16 + 8 + g) * LDA + ks + t;
                af[mi][0] = __float_as_uint(As[r0]);
                af[mi][1] = __float_as_uint(As[r1]);
                af[mi][2] = __float_as_uint(As[r0 + 4]);
                af[mi][3] = __float_as_uint(As[r1 + 4]);
            }
            #pragma unroll
            for (int ni = 0; ni < 4; ni++) {
                int col = wn + ni * 8 + g;
                bf[ni][0] = __float_as_uint(Bs[(ks + t) * LDB + col]);
                bf[ni][1] = __float_as_uint(Bs[(ks + t + 4) * LDB + col]);
            }
            #pragma unroll
            for (int mi = 0; mi < 2; mi++)
                #pragma unroll
                for (int ni = 0; ni < 4; ni++) {
                    asm volatile(
                        "mma.sync.aligned.m16n8k8.row.col.f32.tf32.tf32.f32 "
                        "{%0,%1,%2,%3}, {%4,%5,%6,%7}, {%8,%9}, {%0,%1,%2,%3};\n"
                        : "+f"(c[mi][ni][0]), "+f"(c[mi][ni][1]),
                          "+f"(c[mi][ni][2]), "+f"(c[mi][ni][3])
                        : "r"(af[mi][0]), "r"(af[mi][1]),
                          "r"(af[mi][2]), "r"(af[mi][3]),
                          "r"(bf[ni][0]), "r"(bf[ni][1]));
                }
        }
        __syncthreads();

        if (more) {
            As[am * LDA + ak + 0] = f2tf32(ra0.x);
            As[am * LDA + ak + 1] = f2tf32(ra0.y);
            As[am * LDA + ak + 2] = f2tf32(ra0.z);
            As[am * LDA + ak + 3] = f2tf32(ra0.w);
            As[(am + 64) * LDA + ak + 0] = f2tf32(ra1.x);
            As[(am + 64) * LDA + ak + 1] = f2tf32(ra1.y);
            As[(am + 64) * LDA + ak + 2] = f2tf32(ra1.z);
            As[(am + 64) * LDA + ak + 3] = f2tf32(ra1.w);
            Bs[bk * LDB + bn + 0] = f2tf32(rb.x);
            Bs[bk * LDB + bn + 1] = f2tf32(rb.y);
            Bs[bk * LDB + bn + 2] = f2tf32(rb.z);
            Bs[bk * LDB + bn + 3] = f2tf32(rb.w);
            __syncthreads();
        }
    }

    // ---- epilogue: RoPE on cols < 32 (q,k only), store float2 pairs ----
    const float LOG2_THETA = 13.287712379549449f;  // log2(10000)

    #pragma unroll
    for (int mi = 0; mi < 2; mi++) {
        #pragma unroll
        for (int ni = 0; ni < 4; ni++) {
            int col = n0 + wn + ni * 8 + t * 2;   // even column
            #pragma unroll
            for (int half = 0; half < 2; half++) {
                int row = m0 + wm + mi * 16 + g + half * 8;
                float x1 = c[mi][ni][half * 2 + 0];
                float x2 = c[mi][ni][half * 2 + 1];
                if (rope && col < ROT) {
                    int jh = col >> 1;
                    int tpos = row & (NT - 1);
                    float inv = exp2f(-(float)(2 * jh) * (1.0f / 32.0f) * LOG2_THETA);
                    float ang = (float)tpos * inv;
                    float sn, cs;
                    sincosf(ang, &sn, &cs);
                    float r1 = x1 * cs - x2 * sn;
                    float r2 = x2 * cs + x1 * sn;
                    x1 = r1; x2 = r2;
                }
                *(float2*)&outp[(size_t)row * NH + col] = make_float2(x1, x2);
            }
        }
    }
}

// ============================================================================
// Flash-style causal attention, fp32 (unchanged from R0 baseline).
// Block = (batch b, query tile qt of 64 rows). 256 threads.
// ============================================================================
#define BQ  64
#define BKT 64
#define LDK 68
#define LDS2 68

#define ATTN_SMEM_FLOATS (BQ*NH + NH*LDK + BKT*NH + BQ*LDS2 + 3*BQ)

__global__ __launch_bounds__(256)
void attn_kernel(float* __restrict__ out)
{
    extern __shared__ float sm[];
    float* Qs  = sm;
    float* Kst = Qs  + BQ * NH;
    float* Vs  = Kst + NH * LDK;
    float* Ss  = Vs  + BKT * NH;
    float* m_s = Ss  + BQ * LDS2;
    float* l_s = m_s + BQ;
    float* c_s = l_s + BQ;

    const int b   = blockIdx.y;
    const int qt  = gridDim.x - 1 - blockIdx.x;
    const int q0  = qt * BQ;
    const int tid = threadIdx.x;
    const int tx  = tid & 15;
    const int ty  = tid >> 4;

    {
        const float4* src = (const float4*)(g_q + ((size_t)b * NT + q0) * NH);
        float4* dst = (float4*)Qs;
        #pragma unroll
        for (int i = 0; i < 12; i++)
            dst[tid + i * 256] = src[tid + i * 256];
    }
    if (tid < BQ) { m_s[tid] = -INFINITY; l_s[tid] = 0.f; }

    float o[4][12];
    #pragma unroll
    for (int i = 0; i < 4; i++)
        #pragma unroll
        for (int j = 0; j < 12; j++) o[i][j] = 0.f;

    const float scale = 1.0f / sqrtf((float)NH);

    for (int kt = 0; kt <= qt; kt++) {
        __syncthreads();

        const float* kb = g_k + ((size_t)b * NT + kt * BKT) * NH;
        const float* vb = g_v + ((size_t)b * NT + kt * BKT) * NH;
        for (int e = tid; e < BKT * NH; e += 256) {
            int c = e / NH;
            int h = e - c * NH;
            Kst[h * LDK + c] = kb[e];
        }
        {
            const float4* src = (const float4*)vb;
            float4* dst = (float4*)Vs;
            #pragma unroll
            for (int i = 0; i < 12; i++)
                dst[tid + i * 256] = src[tid + i * 256];
        }
        __syncthreads();

        float s[4][4];
        #pragma unroll
        for (int i = 0; i < 4; i++)
            #pragma unroll
            for (int j = 0; j < 4; j++) s[i][j] = 0.f;

        #pragma unroll 2
        for (int h = 0; h < NH; h += 4) {
            float av[4][4];
            #pragma unroll
            for (int i = 0; i < 4; i++) {
                float4 t4 = *(const float4*)&Qs[(ty * 4 + i) * NH + h];
                av[i][0] = t4.x; av[i][1] = t4.y; av[i][2] = t4.z; av[i][3] = t4.w;
            }
            #pragma unroll
            for (int u = 0; u < 4; u++) {
                float4 bv = *(const float4*)&Kst[(h + u) * LDK + tx * 4];
                float bb[4] = {bv.x, bv.y, bv.z, bv.w};
                #pragma unroll
                for (int i = 0; i < 4; i++)
                    #pragma unroll
                    for (int j = 0; j < 4; j++)
                        s[i][j] += av[i][u] * bb[j];
            }
        }

        const bool diag = (kt == qt);
        #pragma unroll
        for (int i = 0; i < 4; i++) {
            int rq = ty * 4 + i;
            #pragma unroll
            for (int j = 0; j < 4; j++) {
                int cc = tx * 4 + j;
                float v = s[i][j] * scale;
                if (diag && cc > rq) v = -INFINITY;
                Ss[rq * LDS2 + cc] = v;
            }
        }
        __syncthreads();

        if (tid < BQ) {
            int r = tid;
            float mo = m_s[r];
            float rmax = mo;
            #pragma unroll 8
            for (int cc = 0; cc < BKT; cc++)
                rmax = fmaxf(rmax, Ss[r * LDS2 + cc]);
            float corr = expf(mo - rmax);
            float sum = 0.f;
            #pragma unroll 8
            for (int cc = 0; cc < BKT; cc++) {
                float p = expf(Ss[r * LDS2 + cc] - rmax);
                Ss[r * LDS2 + cc] = p;
                sum += p;
            }
            l_s[r] = l_s[r] * corr + sum;
            m_s[r] = rmax;
            c_s[r] = corr;
        }
        __syncthreads();

        #pragma unroll
        for (int i = 0; i < 4; i++) {
            float corr = c_s[ty * 4 + i];
            #pragma unroll
            for (int j = 0; j < 12; j++) o[i][j] *= corr;
        }
        #pragma unroll 2
        for (int kk = 0; kk < BKT; kk++) {
            float p[4];
            #pragma unroll
            for (int i = 0; i < 4; i++)
                p[i] = Ss[(ty * 4 + i) * LDS2 + kk];
            #pragma unroll
            for (int j = 0; j < 12; j++) {
                float vv = Vs[kk * NH + tx + 16 * j];
                #pragma unroll
                for (int i = 0; i < 4; i++)
                    o[i][j] += p[i] * vv;
            }
        }
    }

    float* ob = out + ((size_t)b * NT + q0) * NH;
    #pragma unroll
    for (int i = 0; i < 4; i++) {
        int r = ty * 4 + i;
        float inv_l = 1.0f / l_s[r];
        #pragma unroll
        for (int j = 0; j < 12; j++)
            ob[(size_t)r * NH + tx + 16 * j] = o[i][j] * inv_l;
    }
}

// ============================================================================
// Launch
// ============================================================================
extern "C" void kernel_launch(void* const* d_in, const int* in_sizes, int n_in,
                              void* d_out, int out_size)
{
    const float* x  = (const float*)d_in[0];
    const float* Wq = (const float*)d_in[1];
    const float* Wk = (const float*)d_in[2];
    const float* Wv = (const float*)d_in[3];
    float* out = (float*)d_out;

    (void)in_sizes; (void)n_in; (void)out_size;

    // Fused QKV projections on tensor cores (+RoPE in epilogue for q,k)
    dim3 gblk(256);
    dim3 ggrd(NH / GBN, M_TOT / GBM, 3);   // (3, 256, 3)
    qkv_mma<<<ggrd, gblk>>>(x, Wq, Wk, Wv);

    // Attention (fp32)
    size_t smem = ATTN_SMEM_FLOATS * sizeof(float);
    cudaFuncSetAttribute(attn_kernel, cudaFuncAttributeMaxDynamicSharedMemorySize, (int)smem);
    dim3 agrd(NT / BQ, NB);                // (8, 64)
    attn_kernel<<<agrd, 256, smem>>>(out);
}

// round 5
// speedup vs baseline: 2.8346x; 1.6347x over previous
#include <cuda_runtime.h>
#include <math.h>

#define NB 64
#define NT 512
#define NC 768
#define NH 192
#define ROT 32
#define M_TOT (NB*NT)

// Scratch for projected q, k, v (device globals: no allocation at launch time)
__device__ float g_q[M_TOT * NH];
__device__ float g_k[M_TOT * NH];
__device__ float g_v[M_TOT * NH];

// ============================================================================
// helpers
// ============================================================================
__device__ __forceinline__ float f2tf32(float x) {
    unsigned u;
    asm("cvt.rna.tf32.f32 %0, %1;" : "=r"(u) : "f"(x));
    return __uint_as_float(u);
}
__device__ __forceinline__ float fast_ex2(float x) {
    float y;
    asm("ex2.approx.ftz.f32 %0, %1;" : "=f"(y) : "f"(x));
    return y;
}
#define L2E 1.4426950408889634f

// ============================================================================
// QKV projection: out = X(32768,768) @ W(768,192), RoPE fused for q,k.
// tf32 mma.sync.m16n8k8. Block tile 128x64, BK=16, 256 threads (8 warps 4x2).
// ============================================================================
#define GBM 128
#define GBN 64
#define GBK 16
#define LDA 20
#define LDB 72

__global__ __launch_bounds__(256)
void qkv_mma(const float* __restrict__ X,
             const float* __restrict__ Wq,
             const float* __restrict__ Wk,
             const float* __restrict__ Wv)
{
    __shared__ float As[GBM * LDA];   // [m][k]
    __shared__ float Bs[GBK * LDB];   // [k][n]

    const int which = blockIdx.z;
    const float* W  = (which == 0) ? Wq : (which == 1) ? Wk : Wv;
    float* outp     = (which == 0) ? g_q : (which == 1) ? g_k : g_v;
    const bool rope = (which < 2);

    const int m0 = blockIdx.y * GBM;
    const int n0 = blockIdx.x * GBN;

    const int tid  = threadIdx.x;
    const int lane = tid & 31;
    const int wid  = tid >> 5;
    const int wm   = (wid & 3) * 32;
    const int wn   = (wid >> 2) * 32;
    const int g    = lane >> 2;
    const int t    = lane & 3;

    const int am = tid >> 2;
    const int ak = (tid & 3) * 4;
    const int bk = tid >> 4;
    const int bn = (tid & 15) * 4;

    const float* Ag = X + (size_t)(m0 + am) * NC + ak;
    const float* Bg = W + (size_t)bk * NH + n0 + bn;

    float4 ra0, ra1, rb;

    float c[2][4][4];
    #pragma unroll
    for (int mi = 0; mi < 2; mi++)
        #pragma unroll
        for (int ni = 0; ni < 4; ni++)
            #pragma unroll
            for (int r = 0; r < 4; r++) c[mi][ni][r] = 0.f;

    const int K_TILES = NC / GBK;   // 48

    ra0 = *(const float4*)(Ag);
    ra1 = *(const float4*)(Ag + 64 * NC);
    rb  = *(const float4*)(Bg);
    {
        As[am * LDA + ak + 0] = f2tf32(ra0.x);
        As[am * LDA + ak + 1] = f2tf32(ra0.y);
        As[am * LDA + ak + 2] = f2tf32(ra0.z);
        As[am * LDA + ak + 3] = f2tf32(ra0.w);
        As[(am + 64) * LDA + ak + 0] = f2tf32(ra1.x);
        As[(am + 64) * LDA + ak + 1] = f2tf32(ra1.y);
        As[(am + 64) * LDA + ak + 2] = f2tf32(ra1.z);
        As[(am + 64) * LDA + ak + 3] = f2tf32(ra1.w);
        Bs[bk * LDB + bn + 0] = f2tf32(rb.x);
        Bs[bk * LDB + bn + 1] = f2tf32(rb.y);
        Bs[bk * LDB + bn + 2] = f2tf32(rb.z);
        Bs[bk * LDB + bn + 3] = f2tf32(rb.w);
    }
    __syncthreads();

    for (int kt = 0; kt < K_TILES; kt++) {
        const bool more = (kt + 1 < K_TILES);
        if (more) {
            int k0 = (kt + 1) * GBK;
            ra0 = *(const float4*)(Ag + k0);
            ra1 = *(const float4*)(Ag + 64 * NC + k0);
            rb  = *(const float4*)(Bg + (size_t)k0 * NH);
        }

        #pragma unroll
        for (int ks = 0; ks < GBK; ks += 8) {
            unsigned af[2][4];
            unsigned bf[4][2];
            #pragma unroll
            for (int mi = 0; mi < 2; mi++) {
                int r0 = (wm + mi * 16 + g) * LDA + ks + t;
                int r1 = (wm + mi * 16 + 8 + g) * LDA + ks + t;
                af[mi][0] = __float_as_uint(As[r0]);
                af[mi][1] = __float_as_uint(As[r1]);
                af[mi][2] = __float_as_uint(As[r0 + 4]);
                af[mi][3] = __float_as_uint(As[r1 + 4]);
            }
            #pragma unroll
            for (int ni = 0; ni < 4; ni++) {
                int col = wn + ni * 8 + g;
                bf[ni][0] = __float_as_uint(Bs[(ks + t) * LDB + col]);
                bf[ni][1] = __float_as_uint(Bs[(ks + t + 4) * LDB + col]);
            }
            #pragma unroll
            for (int mi = 0; mi < 2; mi++)
                #pragma unroll
                for (int ni = 0; ni < 4; ni++) {
                    asm volatile(
                        "mma.sync.aligned.m16n8k8.row.col.f32.tf32.tf32.f32 "
                        "{%0,%1,%2,%3}, {%4,%5,%6,%7}, {%8,%9}, {%0,%1,%2,%3};\n"
                        : "+f"(c[mi][ni][0]), "+f"(c[mi][ni][1]),
                          "+f"(c[mi][ni][2]), "+f"(c[mi][ni][3])
                        : "r"(af[mi][0]), "r"(af[mi][1]),
                          "r"(af[mi][2]), "r"(af[mi][3]),
                          "r"(bf[ni][0]), "r"(bf[ni][1]));
                }
        }
        __syncthreads();

        if (more) {
            As[am * LDA + ak + 0] = f2tf32(ra0.x);
            As[am * LDA + ak + 1] = f2tf32(ra0.y);
            As[am * LDA + ak + 2] = f2tf32(ra0.z);
            As[am * LDA + ak + 3] = f2tf32(ra0.w);
            As[(am + 64) * LDA + ak + 0] = f2tf32(ra1.x);
            As[(am + 64) * LDA + ak + 1] = f2tf32(ra1.y);
            As[(am + 64) * LDA + ak + 2] = f2tf32(ra1.z);
            As[(am + 64) * LDA + ak + 3] = f2tf32(ra1.w);
            Bs[bk * LDB + bn + 0] = f2tf32(rb.x);
            Bs[bk * LDB + bn + 1] = f2tf32(rb.y);
            Bs[bk * LDB + bn + 2] = f2tf32(rb.z);
            Bs[bk * LDB + bn + 3] = f2tf32(rb.w);
            __syncthreads();
        }
    }

    const float LOG2_THETA = 13.287712379549449f;

    #pragma unroll
    for (int mi = 0; mi < 2; mi++) {
        #pragma unroll
        for (int ni = 0; ni < 4; ni++) {
            int col = n0 + wn + ni * 8 + t * 2;
            #pragma unroll
            for (int half = 0; half < 2; half++) {
                int row = m0 + wm + mi * 16 + g + half * 8;
                float x1 = c[mi][ni][half * 2 + 0];
                float x2 = c[mi][ni][half * 2 + 1];
                if (rope && col < ROT) {
                    int jh = col >> 1;
                    int tpos = row & (NT - 1);
                    float inv = exp2f(-(float)(2 * jh) * (1.0f / 32.0f) * LOG2_THETA);
                    float ang = (float)tpos * inv;
                    float sn, cs;
                    sincosf(ang, &sn, &cs);
                    float r1 = x1 * cs - x2 * sn;
                    float r2 = x2 * cs + x1 * sn;
                    x1 = r1; x2 = r2;
                }
                *(float2*)&outp[(size_t)row * NH + col] = make_float2(x1, x2);
            }
        }
    }
}

// ============================================================================
// Tensor-core flash attention (tf32 mma for S=QK^T and O=PV).
// Block = (batch b, query tile of 64 rows). 256 threads = 8 warps.
// ============================================================================
#define BQ  64
#define BKT 64
#define LDQ 196  // Q/K smem row stride (floats): frag bank = 4*row+t, unique
#define LDV 200  // V smem row stride: frag bank = 8*t+g, unique
#define LDS 68   // S smem row stride: frag bank = 4*row+t, unique

#define ATTN_SMEM_FLOATS (BQ*LDQ + BKT*LDQ + BKT*LDV + BQ*LDS + 3*BQ)

__global__ __launch_bounds__(256)
void attn_mma(float* __restrict__ out)
{
    extern __shared__ float sm[];
    float* Qs  = sm;                  // [64][LDQ]
    float* Ks  = Qs  + BQ * LDQ;      // [64][LDQ]  natural row-major
    float* Vs  = Ks  + BKT * LDQ;     // [64][LDV]  natural row-major
    float* Ss  = Vs  + BKT * LDV;     // [64][LDS]
    float* m_s = Ss  + BQ * LDS;      // [64]
    float* l_s = m_s + BQ;            // [64]
    float* c_s = l_s + BQ;            // [64]

    const int b   = blockIdx.y;
    const int qt  = gridDim.x - 1 - blockIdx.x;   // heavy tiles first
    const int q0  = qt * BQ;
    const int tid = threadIdx.x;
    const int lane = tid & 31;
    const int wid  = tid >> 5;
    const int g    = lane >> 2;       // 0..7
    const int t    = lane & 3;        // 0..3
    const int wm   = (wid & 3) * 16;  // warp M offset (rows)
    const int wns  = (wid >> 2) * 32; // warp N offset for S
    const int wnv  = (wid >> 2) * 96; // warp N offset for PV / O

    // ---- load Q tile (tf32-rounded) ----
    {
        const float4* src = (const float4*)(g_q + ((size_t)b * NT + q0) * NH);
        #pragma unroll
        for (int i = 0; i < 12; i++) {
            int e = tid + i * 256;          // 0..3071 float4s
            int row = e / 48, c4 = e - row * 48;
            float4 v = src[e];
            v.x = f2tf32(v.x); v.y = f2tf32(v.y);
            v.z = f2tf32(v.z); v.w = f2tf32(v.w);
            *(float4*)&Qs[row * LDQ + c4 * 4] = v;
        }
    }
    if (tid < BQ) { m_s[tid] = -INFINITY; l_s[tid] = 0.f; }

    float o[12][4];
    #pragma unroll
    for (int ni = 0; ni < 12; ni++)
        #pragma unroll
        for (int r = 0; r < 4; r++) o[ni][r] = 0.f;

    const float scale = 1.0f / sqrtf((float)NH);

    for (int kt = 0; kt <= qt; kt++) {
        __syncthreads();   // prev PV done before K/V/S overwrite

        // ---- load K, V tiles (tf32-rounded) ----
        {
            const float4* ksrc = (const float4*)(g_k + ((size_t)b * NT + kt * BKT) * NH);
            const float4* vsrc = (const float4*)(g_v + ((size_t)b * NT + kt * BKT) * NH);
            #pragma unroll
            for (int i = 0; i < 12; i++) {
                int e = tid + i * 256;
                int row = e / 48, c4 = e - row * 48;
                float4 kv = ksrc[e];
                kv.x = f2tf32(kv.x); kv.y = f2tf32(kv.y);
                kv.z = f2tf32(kv.z); kv.w = f2tf32(kv.w);
                *(float4*)&Ks[row * LDQ + c4 * 4] = kv;
                float4 vv = vsrc[e];
                vv.x = f2tf32(vv.x); vv.y = f2tf32(vv.y);
                vv.z = f2tf32(vv.z); vv.w = f2tf32(vv.w);
                *(float4*)&Vs[row * LDV + c4 * 4] = vv;
            }
        }
        __syncthreads();

        // ---- S = Q K^T via mma (each warp: 16 rows x 32 cols) ----
        float s[4][4];
        #pragma unroll
        for (int ni = 0; ni < 4; ni++)
            #pragma unroll
            for (int r = 0; r < 4; r++) s[ni][r] = 0.f;

        #pragma unroll 4
        for (int ks = 0; ks < NH; ks += 8) {
            unsigned af[4];
            int r0 = (wm + g) * LDQ + ks + t;
            int r1 = (wm + 8 + g) * LDQ + ks + t;
            af[0] = __float_as_uint(Qs[r0]);
            af[1] = __float_as_uint(Qs[r1]);
            af[2] = __float_as_uint(Qs[r0 + 4]);
            af[3] = __float_as_uint(Qs[r1 + 4]);
            #pragma unroll
            for (int ni = 0; ni < 4; ni++) {
                int col = wns + ni * 8 + g;
                unsigned b0 = __float_as_uint(Ks[col * LDQ + ks + t]);
                unsigned b1 = __float_as_uint(Ks[col * LDQ + ks + t + 4]);
                asm volatile(
                    "mma.sync.aligned.m16n8k8.row.col.f32.tf32.tf32.f32 "
                    "{%0,%1,%2,%3}, {%4,%5,%6,%7}, {%8,%9}, {%0,%1,%2,%3};\n"
                    : "+f"(s[ni][0]), "+f"(s[ni][1]), "+f"(s[ni][2]), "+f"(s[ni][3])
                    : "r"(af[0]), "r"(af[1]), "r"(af[2]), "r"(af[3]),
                      "r"(b0), "r"(b1));
            }
        }

        // ---- scale + causal mask, write S to smem ----
        const bool diag = (kt == qt);
        #pragma unroll
        for (int ni = 0; ni < 4; ni++) {
            #pragma unroll
            for (int half = 0; half < 2; half++) {
                int row = wm + half * 8 + g;
                #pragma unroll
                for (int j = 0; j < 2; j++) {
                    int col = wns + ni * 8 + t * 2 + j;
                    float v = s[ni][half * 2 + j] * scale;
                    if (diag && col > row) v = -INFINITY;
                    Ss[row * LDS + col] = v;
                }
            }
        }
        __syncthreads();

        // ---- online softmax: 4 threads per row, 16 cols each ----
        {
            int r   = tid >> 2;
            int sub = tid & 3;
            float* rp = Ss + r * LDS + sub * 16;

            float p[16];                       // proper array: indexable
            *(float4*)(p + 0)  = *(float4*)(rp + 0);
            *(float4*)(p + 4)  = *(float4*)(rp + 4);
            *(float4*)(p + 8)  = *(float4*)(rp + 8);
            *(float4*)(p + 12) = *(float4*)(rp + 12);

            float tmax = p[0];
            #pragma unroll
            for (int i = 1; i < 16; i++) tmax = fmaxf(tmax, p[i]);
            tmax = fmaxf(tmax, __shfl_xor_sync(0xffffffffu, tmax, 1));
            tmax = fmaxf(tmax, __shfl_xor_sync(0xffffffffu, tmax, 2));

            float mo   = m_s[r];
            float rmax = fmaxf(mo, tmax);
            float corr = fast_ex2((mo - rmax) * L2E);

            float sum = 0.f;
            #pragma unroll
            for (int i = 0; i < 16; i++) {
                float e = fast_ex2((p[i] - rmax) * L2E);
                sum += e;
                p[i] = f2tf32(e);
            }
            *(float4*)(rp + 0)  = *(float4*)(p + 0);
            *(float4*)(rp + 4)  = *(float4*)(p + 4);
            *(float4*)(rp + 8)  = *(float4*)(p + 8);
            *(float4*)(rp + 12) = *(float4*)(p + 12);

            sum += __shfl_xor_sync(0xffffffffu, sum, 1);
            sum += __shfl_xor_sync(0xffffffffu, sum, 2);
            if (sub == 0) {
                l_s[r] = l_s[r] * corr + sum;
                m_s[r] = rmax;
                c_s[r] = corr;
            }
        }
        __syncthreads();

        // ---- O = O*corr + P V via mma (each warp: 16 rows x 96 cols) ----
        {
            float corr0 = c_s[wm + g];
            float corr1 = c_s[wm + 8 + g];
            #pragma unroll
            for (int ni = 0; ni < 12; ni++) {
                o[ni][0] *= corr0; o[ni][1] *= corr0;
                o[ni][2] *= corr1; o[ni][3] *= corr1;
            }
        }
        #pragma unroll
        for (int kk = 0; kk < BKT; kk += 8) {
            unsigned af[4];
            int r0 = (wm + g) * LDS + kk + t;
            int r1 = (wm + 8 + g) * LDS + kk + t;
            af[0] = __float_as_uint(Ss[r0]);
            af[1] = __float_as_uint(Ss[r1]);
            af[2] = __float_as_uint(Ss[r0 + 4]);
            af[3] = __float_as_uint(Ss[r1 + 4]);
            #pragma unroll
            for (int ni = 0; ni < 12; ni++) {
                int col = wnv + ni * 8 + g;
                unsigned b0 = __float_as_uint(Vs[(kk + t) * LDV + col]);
                unsigned b1 = __float_as_uint(Vs[(kk + t + 4) * LDV + col]);
                asm volatile(
                    "mma.sync.aligned.m16n8k8.row.col.f32.tf32.tf32.f32 "
                    "{%0,%1,%2,%3}, {%4,%5,%6,%7}, {%8,%9}, {%0,%1,%2,%3};\n"
                    : "+f"(o[ni][0]), "+f"(o[ni][1]), "+f"(o[ni][2]), "+f"(o[ni][3])
                    : "r"(af[0]), "r"(af[1]), "r"(af[2]), "r"(af[3]),
                      "r"(b0), "r"(b1));
            }
        }
    }

    // ---- finalize: O / l, store ----
    __syncthreads();
    {
        float inv0 = 1.0f / l_s[wm + g];
        float inv1 = 1.0f / l_s[wm + 8 + g];
        float* ob = out + ((size_t)b * NT + q0) * NH;
        #pragma unroll
        for (int ni = 0; ni < 12; ni++) {
            int col = wnv + ni * 8 + t * 2;
            int row0 = wm + g;
            int row1 = wm + 8 + g;
            *(float2*)&ob[(size_t)row0 * NH + col] =
                make_float2(o[ni][0] * inv0, o[ni][1] * inv0);
            *(float2*)&ob[(size_t)row1 * NH + col] =
                make_float2(o[ni][2] * inv1, o[ni][3] * inv1);
        }
    }
}

// ============================================================================
// Launch
// ============================================================================
extern "C" void kernel_launch(void* const* d_in, const int* in_sizes, int n_in,
                              void* d_out, int out_size)
{
    const float* x  = (const float*)d_in[0];
    const float* Wq = (const float*)d_in[1];
    const float* Wk = (const float*)d_in[2];
    const float* Wv = (const float*)d_in[3];
    float* out = (float*)d_out;

    (void)in_sizes; (void)n_in; (void)out_size;

    dim3 gblk(256);
    dim3 ggrd(NH / GBN, M_TOT / GBM, 3);
    qkv_mma<<<ggrd, gblk>>>(x, Wq, Wk, Wv);

    size_t smem = ATTN_SMEM_FLOATS * sizeof(float);
    cudaFuncSetAttribute(attn_mma, cudaFuncAttributeMaxDynamicSharedMemorySize, (int)smem);
    dim3 agrd(NT / BQ, NB);
    attn_mma<<<agrd, 256, smem>>>(out);
}

// round 8
// speedup vs baseline: 2.8743x; 1.0140x over previous
#include <cuda_runtime.h>
#include <math.h>

#define NB 64
#define NT 512
#define NC 768
#define NH 192
#define ROT 32
#define M_TOT (NB*NT)

// Scratch for projected q, k, v (device globals: no allocation at launch time)
__device__ float g_q[M_TOT * NH];
__device__ float g_k[M_TOT * NH];
__device__ float g_v[M_TOT * NH];

// ============================================================================
// helpers
// ============================================================================
__device__ __forceinline__ float f2tf32(float x) {
    unsigned u;
    asm("cvt.rna.tf32.f32 %0, %1;" : "=r"(u) : "f"(x));
    return __uint_as_float(u);
}
__device__ __forceinline__ float4 f2tf32_4(float4 v) {
    return make_float4(f2tf32(v.x), f2tf32(v.y), f2tf32(v.z), f2tf32(v.w));
}
__device__ __forceinline__ float fast_ex2(float x) {
    float y;
    asm("ex2.approx.ftz.f32 %0, %1;" : "=f"(y) : "f"(x));
    return y;
}
#define L2E 1.4426950408889634f

// ============================================================================
// QKV projection: out = X(32768,768) @ W(768,192), RoPE fused for q,k.
// tf32 mma.sync.m16n8k8. Block tile 128x64, BK=16, 256 threads (8 warps 4x2).
// Double-buffered smem, float4 smem fills, one sync per k-tile.
// ============================================================================
#define GBM 128
#define GBN 64
#define GBK 16
#define LDA 20
#define LDB 72

__global__ __launch_bounds__(256)
void qkv_mma(const float* __restrict__ X,
             const float* __restrict__ Wq,
             const float* __restrict__ Wk,
             const float* __restrict__ Wv)
{
    __shared__ float As[2][GBM * LDA];   // [m][k]
    __shared__ float Bs[2][GBK * LDB];   // [k][n]

    const int which = blockIdx.z;
    const float* W  = (which == 0) ? Wq : (which == 1) ? Wk : Wv;
    float* outp     = (which == 0) ? g_q : (which == 1) ? g_k : g_v;
    const bool rope = (which < 2);

    const int m0 = blockIdx.y * GBM;
    const int n0 = blockIdx.x * GBN;

    const int tid  = threadIdx.x;
    const int lane = tid & 31;
    const int wid  = tid >> 5;
    const int wm   = (wid & 3) * 32;
    const int wn   = (wid >> 2) * 32;
    const int g    = lane >> 2;
    const int t    = lane & 3;

    const int am = tid >> 2;           // 0..63
    const int ak = (tid & 3) * 4;      // 0,4,8,12
    const int bk = tid >> 4;           // 0..15
    const int bn = (tid & 15) * 4;     // 0..60

    const float* Ag = X + (size_t)(m0 + am) * NC + ak;
    const float* Bg = W + (size_t)bk * NH + n0 + bn;

    float4 ra0, ra1, rb;

    float c[2][4][4];
    #pragma unroll
    for (int mi = 0; mi < 2; mi++)
        #pragma unroll
        for (int ni = 0; ni < 4; ni++)
            #pragma unroll
            for (int r = 0; r < 4; r++) c[mi][ni][r] = 0.f;

    const int K_TILES = NC / GBK;   // 48

    // prologue: load + store tile 0
    ra0 = *(const float4*)(Ag);
    ra1 = *(const float4*)(Ag + 64 * NC);
    rb  = *(const float4*)(Bg);
    *(float4*)&As[0][am * LDA + ak]        = f2tf32_4(ra0);
    *(float4*)&As[0][(am + 64) * LDA + ak] = f2tf32_4(ra1);
    *(float4*)&Bs[0][bk * LDB + bn]        = f2tf32_4(rb);
    __syncthreads();

    for (int kt = 0; kt < K_TILES; kt++) {
        const int cur = kt & 1;
        const bool more = (kt + 1 < K_TILES);
        if (more) {
            int k0 = (kt + 1) * GBK;
            ra0 = *(const float4*)(Ag + k0);
            ra1 = *(const float4*)(Ag + 64 * NC + k0);
            rb  = *(const float4*)(Bg + (size_t)k0 * NH);
        }

        const float* Ac = As[cur];
        const float* Bc = Bs[cur];
        #pragma unroll
        for (int ks = 0; ks < GBK; ks += 8) {
            unsigned af[2][4];
            unsigned bf[4][2];
            #pragma unroll
            for (int mi = 0; mi < 2; mi++) {
                int r0 = (wm + mi * 16 + g) * LDA + ks + t;
                int r1 = (wm + mi * 16 + 8 + g) * LDA + ks + t;
                af[mi][0] = __float_as_uint(Ac[r0]);
                af[mi][1] = __float_as_uint(Ac[r1]);
                af[mi][2] = __float_as_uint(Ac[r0 + 4]);
                af[mi][3] = __float_as_uint(Ac[r1 + 4]);
            }
            #pragma unroll
            for (int ni = 0; ni < 4; ni++) {
                int col = wn + ni * 8 + g;
                bf[ni][0] = __float_as_uint(Bc[(ks + t) * LDB + col]);
                bf[ni][1] = __float_as_uint(Bc[(ks + t + 4) * LDB + col]);
            }
            #pragma unroll
            for (int mi = 0; mi < 2; mi++)
                #pragma unroll
                for (int ni = 0; ni < 4; ni++) {
                    asm volatile(
                        "mma.sync.aligned.m16n8k8.row.col.f32.tf32.tf32.f32 "
                        "{%0,%1,%2,%3}, {%4,%5,%6,%7}, {%8,%9}, {%0,%1,%2,%3};\n"
                        : "+f"(c[mi][ni][0]), "+f"(c[mi][ni][1]),
                          "+f"(c[mi][ni][2]), "+f"(c[mi][ni][3])
                        : "r"(af[mi][0]), "r"(af[mi][1]),
                          "r"(af[mi][2]), "r"(af[mi][3]),
                          "r"(bf[ni][0]), "r"(bf[ni][1]));
                }
        }

        if (more) {
            const int nxt = cur ^ 1;
            *(float4*)&As[nxt][am * LDA + ak]        = f2tf32_4(ra0);
            *(float4*)&As[nxt][(am + 64) * LDA + ak] = f2tf32_4(ra1);
            *(float4*)&Bs[nxt][bk * LDB + bn]        = f2tf32_4(rb);
            __syncthreads();
        }
    }

    const float LOG2_THETA = 13.287712379549449f;

    #pragma unroll
    for (int mi = 0; mi < 2; mi++) {
        #pragma unroll
        for (int ni = 0; ni < 4; ni++) {
            int col = n0 + wn + ni * 8 + t * 2;
            #pragma unroll
            for (int half = 0; half < 2; half++) {
                int row = m0 + wm + mi * 16 + g + half * 8;
                float x1 = c[mi][ni][half * 2 + 0];
                float x2 = c[mi][ni][half * 2 + 1];
                if (rope && col < ROT) {
                    int jh = col >> 1;
                    int tpos = row & (NT - 1);
                    float inv = exp2f(-(float)(2 * jh) * (1.0f / 32.0f) * LOG2_THETA);
                    float ang = (float)tpos * inv;
                    float sn, cs;
                    sincosf(ang, &sn, &cs);
                    float r1 = x1 * cs - x2 * sn;
                    float r2 = x2 * cs + x1 * sn;
                    x1 = r1; x2 = r2;
                }
                *(float2*)&outp[(size_t)row * NH + col] = make_float2(x1, x2);
            }
        }
    }
}

// ============================================================================
// Tensor-core flash attention (tf32 mma for S=QK^T and O=PV).
// Block = (batch b, query tile of 64 rows). 256 threads = 8 warps.
// ============================================================================
#define BQ  64
#define BKT 64
#define LDQ 196  // Q/K smem row stride (floats): frag bank = 4*row+t, unique
#define LDV 200  // V smem row stride: frag bank = 8*t+g, unique
#define LDS 68   // S smem row stride: frag bank = 4*row+t, unique

#define ATTN_SMEM_FLOATS (BQ*LDQ + BKT*LDQ + BKT*LDV + BQ*LDS + 3*BQ)

__global__ __launch_bounds__(256)
void attn_mma(float* __restrict__ out)
{
    extern __shared__ float sm[];
    float* Qs  = sm;                  // [64][LDQ]
    float* Ks  = Qs  + BQ * LDQ;      // [64][LDQ]  natural row-major
    float* Vs  = Ks  + BKT * LDQ;     // [64][LDV]  natural row-major
    float* Ss  = Vs  + BKT * LDV;     // [64][LDS]
    float* m_s = Ss  + BQ * LDS;      // [64]
    float* l_s = m_s + BQ;            // [64]
    float* c_s = l_s + BQ;            // [64]

    const int b   = blockIdx.y;
    const int qt  = gridDim.x - 1 - blockIdx.x;   // heavy tiles first
    const int q0  = qt * BQ;
    const int tid = threadIdx.x;
    const int lane = tid & 31;
    const int wid  = tid >> 5;
    const int g    = lane >> 2;       // 0..7
    const int t    = lane & 3;        // 0..3
    const int wm   = (wid & 3) * 16;  // warp M offset (rows)
    const int wns  = (wid >> 2) * 32; // warp N offset for S
    const int wnv  = (wid >> 2) * 96; // warp N offset for PV / O

    // ---- load Q tile (tf32-rounded) ----
    {
        const float4* src = (const float4*)(g_q + ((size_t)b * NT + q0) * NH);
        #pragma unroll
        for (int i = 0; i < 12; i++) {
            int e = tid + i * 256;          // 0..3071 float4s
            int row = e / 48, c4 = e - row * 48;
            float4 v = src[e];
            *(float4*)&Qs[row * LDQ + c4 * 4] = f2tf32_4(v);
        }
    }
    if (tid < BQ) { m_s[tid] = -INFINITY; l_s[tid] = 0.f; }

    float o[12][4];
    #pragma unroll
    for (int ni = 0; ni < 12; ni++)
        #pragma unroll
        for (int r = 0; r < 4; r++) o[ni][r] = 0.f;

    const float scale = 1.0f / sqrtf((float)NH);

    for (int kt = 0; kt <= qt; kt++) {
        __syncthreads();   // prev PV done before K/V/S overwrite

        // ---- load K, V tiles (tf32-rounded) ----
        {
            const float4* ksrc = (const float4*)(g_k + ((size_t)b * NT + kt * BKT) * NH);
            const float4* vsrc = (const float4*)(g_v + ((size_t)b * NT + kt * BKT) * NH);
            #pragma unroll
            for (int i = 0; i < 12; i++) {
                int e = tid + i * 256;
                int row = e / 48, c4 = e - row * 48;
                float4 kv = ksrc[e];
                *(float4*)&Ks[row * LDQ + c4 * 4] = f2tf32_4(kv);
                float4 vv = vsrc[e];
                *(float4*)&Vs[row * LDV + c4 * 4] = f2tf32_4(vv);
            }
        }
        __syncthreads();

        // ---- S = Q K^T via mma (each warp: 16 rows x 32 cols) ----
        float s[4][4];
        #pragma unroll
        for (int ni = 0; ni < 4; ni++)
            #pragma unroll
            for (int r = 0; r < 4; r++) s[ni][r] = 0.f;

        #pragma unroll 4
        for (int ks = 0; ks < NH; ks += 8) {
            unsigned af[4];
            int r0 = (wm + g) * LDQ + ks + t;
            int r1 = (wm + 8 + g) * LDQ + ks + t;
            af[0] = __float_as_uint(Qs[r0]);
            af[1] = __float_as_uint(Qs[r1]);
            af[2] = __float_as_uint(Qs[r0 + 4]);
            af[3] = __float_as_uint(Qs[r1 + 4]);
            #pragma unroll
            for (int ni = 0; ni < 4; ni++) {
                int col = wns + ni * 8 + g;
                unsigned b0 = __float_as_uint(Ks[col * LDQ + ks + t]);
                unsigned b1 = __float_as_uint(Ks[col * LDQ + ks + t + 4]);
                asm volatile(
                    "mma.sync.aligned.m16n8k8.row.col.f32.tf32.tf32.f32 "
                    "{%0,%1,%2,%3}, {%4,%5,%6,%7}, {%8,%9}, {%0,%1,%2,%3};\n"
                    : "+f"(s[ni][0]), "+f"(s[ni][1]), "+f"(s[ni][2]), "+f"(s[ni][3])
                    : "r"(af[0]), "r"(af[1]), "r"(af[2]), "r"(af[3]),
                      "r"(b0), "r"(b1));
            }
        }

        // ---- scale + causal mask, write S to smem ----
        const bool diag = (kt == qt);
        #pragma unroll
        for (int ni = 0; ni < 4; ni++) {
            #pragma unroll
            for (int half = 0; half < 2; half++) {
                int row = wm + half * 8 + g;
                #pragma unroll
                for (int j = 0; j < 2; j++) {
                    int col = wns + ni * 8 + t * 2 + j;
                    float v = s[ni][half * 2 + j] * scale;
                    if (diag && col > row) v = -INFINITY;
                    Ss[row * LDS + col] = v;
                }
            }
        }
        __syncthreads();

        // ---- online softmax: 4 threads per row, 16 cols each ----
        {
            int r   = tid >> 2;
            int sub = tid & 3;
            float* rp = Ss + r * LDS + sub * 16;

            float p[16];
            *(float4*)(p + 0)  = *(float4*)(rp + 0);
            *(float4*)(p + 4)  = *(float4*)(rp + 4);
            *(float4*)(p + 8)  = *(float4*)(rp + 8);
            *(float4*)(p + 12) = *(float4*)(rp + 12);

            float tmax = p[0];
            #pragma unroll
            for (int i = 1; i < 16; i++) tmax = fmaxf(tmax, p[i]);
            tmax = fmaxf(tmax, __shfl_xor_sync(0xffffffffu, tmax, 1));
            tmax = fmaxf(tmax, __shfl_xor_sync(0xffffffffu, tmax, 2));

            float mo   = m_s[r];
            float rmax = fmaxf(mo, tmax);
            float corr = fast_ex2((mo - rmax) * L2E);

            float sum = 0.f;
            #pragma unroll
            for (int i = 0; i < 16; i++) {
                float e = fast_ex2((p[i] - rmax) * L2E);
                sum += e;
                p[i] = f2tf32(e);
            }
            *(float4*)(rp + 0)  = *(float4*)(p + 0);
            *(float4*)(rp + 4)  = *(float4*)(p + 4);
            *(float4*)(rp + 8)  = *(float4*)(p + 8);
            *(float4*)(rp + 12) = *(float4*)(p + 12);

            sum += __shfl_xor_sync(0xffffffffu, sum, 1);
            sum += __shfl_xor_sync(0xffffffffu, sum, 2);
            if (sub == 0) {
                l_s[r] = l_s[r] * corr + sum;
                m_s[r] = rmax;
                c_s[r] = corr;
            }
        }
        __syncthreads();

        // ---- O = O*corr + P V via mma (each warp: 16 rows x 96 cols) ----
        {
            float corr0 = c_s[wm + g];
            float corr1 = c_s[wm + 8 + g];
            #pragma unroll
            for (int ni = 0; ni < 12; ni++) {
                o[ni][0] *= corr0; o[ni][1] *= corr0;
                o[ni][2] *= corr1; o[ni][3] *= corr1;
            }
        }
        #pragma unroll
        for (int kk = 0; kk < BKT; kk += 8) {
            unsigned af[4];
            int r0 = (wm + g) * LDS + kk + t;
            int r1 = (wm + 8 + g) * LDS + kk + t;
            af[0] = __float_as_uint(Ss[r0]);
            af[1] = __float_as_uint(Ss[r1]);
            af[2] = __float_as_uint(Ss[r0 + 4]);
            af[3] = __float_as_uint(Ss[r1 + 4]);
            #pragma unroll
            for (int ni = 0; ni < 12; ni++) {
                int col = wnv + ni * 8 + g;
                unsigned b0 = __float_as_uint(Vs[(kk + t) * LDV + col]);
                unsigned b1 = __float_as_uint(Vs[(kk + t + 4) * LDV + col]);
                asm volatile(
                    "mma.sync.aligned.m16n8k8.row.col.f32.tf32.tf32.f32 "
                    "{%0,%1,%2,%3}, {%4,%5,%6,%7}, {%8,%9}, {%0,%1,%2,%3};\n"
                    : "+f"(o[ni][0]), "+f"(o[ni][1]), "+f"(o[ni][2]), "+f"(o[ni][3])
                    : "r"(af[0]), "r"(af[1]), "r"(af[2]), "r"(af[3]),
                      "r"(b0), "r"(b1));
            }
        }
    }

    // ---- finalize: O / l, store ----
    __syncthreads();
    {
        float inv0 = 1.0f / l_s[wm + g];
        float inv1 = 1.0f / l_s[wm + 8 + g];
        float* ob = out + ((size_t)b * NT + q0) * NH;
        #pragma unroll
        for (int ni = 0; ni < 12; ni++) {
            int col = wnv + ni * 8 + t * 2;
            int row0 = wm + g;
            int row1 = wm + 8 + g;
            *(float2*)&ob[(size_t)row0 * NH + col] =
                make_float2(o[ni][0] * inv0, o[ni][1] * inv0);
            *(float2*)&ob[(size_t)row1 * NH + col] =
                make_float2(o[ni][2] * inv1, o[ni][3] * inv1);
        }
    }
}

// ============================================================================
// Launch
// ============================================================================
extern "C" void kernel_launch(void* const* d_in, const int* in_sizes, int n_in,
                              void* d_out, int out_size)
{
    const float* x  = (const float*)d_in[0];
    const float* Wq = (const float*)d_in[1];
    const float* Wk = (const float*)d_in[2];
    const float* Wv = (const float*)d_in[3];
    float* out = (float*)d_out;

    (void)in_sizes; (void)n_in; (void)out_size;

    dim3 gblk(256);
    dim3 ggrd(NH / GBN, M_TOT / GBM, 3);
    qkv_mma<<<ggrd, gblk>>>(x, Wq, Wk, Wv);

    size_t smem = ATTN_SMEM_FLOATS * sizeof(float);
    cudaFuncSetAttribute(attn_mma, cudaFuncAttributeMaxDynamicSharedMemorySize, (int)smem);
    dim3 agrd(NT / BQ, NB);
    attn_mma<<<agrd, 256, smem>>>(out);
}